// round 13
// baseline (speedup 1.0000x reference)
#include <cuda_runtime.h>
#include <cuda_fp16.h>
#include <cstdint>
#include <math.h>

#define B_  8
#define N_  512
#define D_  512
#define H_  8
#define DH_ 64
#define E_  32768
#define BN_ (B_ * N_)          // 4096 rows

// -------------------- scratch (device globals) -----------------------------
__device__ __half g_qh[BN_ * D_];
__device__ __half g_kh[BN_ * D_];
__device__ __half g_vh[BN_ * D_];
__device__ float  g_ctx[BN_ * D_];
__device__ float  g_bias[B_ * N_ * N_];
__device__ __half g_wqt[D_ * D_];   // W^T fp16, [n][k]
__device__ __half g_wkt[D_ * D_];
__device__ __half g_wvt[D_ * D_];
__device__ __half g_wot[D_ * D_];

// -------------------- helpers ----------------------------------------------
__device__ __forceinline__ uint32_t smem_u32(const void* p) {
    uint32_t a;
    asm("{ .reg .u64 t; cvta.to.shared.u64 t, %1; cvt.u32.u64 %0, t; }"
        : "=r"(a) : "l"(p));
    return a;
}
__device__ __forceinline__ uint32_t pack_half2(float x, float y) {
    __half2 h = __floats2half2_rn(x, y);
    return *(uint32_t*)&h;
}
__device__ __forceinline__ void mma_f16(float* d, const uint32_t* a, const uint32_t* b) {
    asm volatile(
        "mma.sync.aligned.m16n8k16.row.col.f32.f16.f16.f32 "
        "{%0,%1,%2,%3}, {%4,%5,%6,%7}, {%8,%9}, {%0,%1,%2,%3};\n"
        : "+f"(d[0]), "+f"(d[1]), "+f"(d[2]), "+f"(d[3])
        : "r"(a[0]), "r"(a[1]), "r"(a[2]), "r"(a[3]), "r"(b[0]), "r"(b[1]));
}
__device__ __forceinline__ void ldsm_x4(uint32_t& r0, uint32_t& r1,
                                        uint32_t& r2, uint32_t& r3, uint32_t a) {
    asm volatile("ldmatrix.sync.aligned.m8n8.x4.shared.b16 {%0,%1,%2,%3}, [%4];"
                 : "=r"(r0), "=r"(r1), "=r"(r2), "=r"(r3) : "r"(a));
}
__device__ __forceinline__ void ldsm_x2(uint32_t& r0, uint32_t& r1, uint32_t a) {
    asm volatile("ldmatrix.sync.aligned.m8n8.x2.shared.b16 {%0,%1}, [%2];"
                 : "=r"(r0), "=r"(r1) : "r"(a));
}
__device__ __forceinline__ void ldsm_x4t(uint32_t& r0, uint32_t& r1,
                                         uint32_t& r2, uint32_t& r3, uint32_t a) {
    asm volatile("ldmatrix.sync.aligned.m8n8.x4.trans.shared.b16 {%0,%1,%2,%3}, [%4];"
                 : "=r"(r0), "=r"(r1), "=r"(r2), "=r"(r3) : "r"(a));
}
__device__ __forceinline__ void cp16(uint32_t s, const void* g) {
    asm volatile("cp.async.cg.shared.global [%0], [%1], 16;" :: "r"(s), "l"(g));
}
__device__ __forceinline__ void cp_commit() {
    asm volatile("cp.async.commit_group;" ::: "memory");
}
__device__ __forceinline__ void cp_wait0() {
    asm volatile("cp.async.wait_group 0;" ::: "memory");
}

// -------------------- fp16 tensor-core GEMM (double-buffered) ---------------
// C[4096,512] tile: BM = 32*MT rows x 128 cols, KB=32, 256 threads = 8 warps
// (2m x 4n); warp tile (16*MT) x 32. MT=4 -> 128x128, MT=2 -> 64x128.
#define GP 40
template <int MT, bool HALF_OUT>
__device__ __forceinline__ void gemm_body(const float* __restrict__ A,
                                          const __half* __restrict__ Bt,
                                          void* __restrict__ Cv,
                                          int bm, int bn) {
    __shared__ __half As[2][32 * MT][GP];   // [m][k]
    __shared__ __half Bs[2][128][GP];       // [n][k]

    const int tid  = threadIdx.x;
    const int lane = tid & 31;
    const int wid  = tid >> 5;
    const int wm   = (wid & 1) * (16 * MT);
    const int wn   = (wid >> 1) * 32;

    float acc[MT][4][4];
#pragma unroll
    for (int mt = 0; mt < MT; ++mt)
#pragma unroll
        for (int nt = 0; nt < 4; ++nt)
#pragma unroll
            for (int i = 0; i < 4; ++i) acc[mt][nt][i] = 0.f;

    const int am = tid >> 3, akq = tid & 7;
    const int bn_r = tid >> 2, bseg = tid & 3;

    float4 pa[MT];
    uint4  pb[2];
#pragma unroll
    for (int it = 0; it < MT; ++it)
        pa[it] = *(const float4*)&A[(size_t)(bm + am + it * 32) * 512 + akq * 4];
#pragma unroll
    for (int it = 0; it < 2; ++it)
        pb[it] = *(const uint4*)&Bt[(size_t)(bn + bn_r + it * 64) * 512 + bseg * 8];
#pragma unroll
    for (int it = 0; it < MT; ++it) {
        float4 v = pa[it];
        *(uint2*)&As[0][am + it * 32][akq * 4] =
            make_uint2(pack_half2(v.x, v.y), pack_half2(v.z, v.w));
    }
#pragma unroll
    for (int it = 0; it < 2; ++it)
        *(uint4*)&Bs[0][bn_r + it * 64][bseg * 8] = pb[it];
    __syncthreads();

#pragma unroll 2
    for (int ch = 0; ch < 16; ++ch) {
        const int cur = ch & 1, nxt = cur ^ 1;
        if (ch < 15) {
            const int k0 = (ch + 1) * 32;
#pragma unroll
            for (int it = 0; it < MT; ++it)
                pa[it] = *(const float4*)&A[(size_t)(bm + am + it * 32) * 512 + k0 + akq * 4];
#pragma unroll
            for (int it = 0; it < 2; ++it)
                pb[it] = *(const uint4*)&Bt[(size_t)(bn + bn_r + it * 64) * 512 + k0 + bseg * 8];
        }

#pragma unroll
        for (int ks = 0; ks < 2; ++ks) {
            const int k16 = ks * 16;
            uint32_t afr[MT][4], bfr[4][2];
#pragma unroll
            for (int mt = 0; mt < MT; ++mt)
                ldsm_x4(afr[mt][0], afr[mt][1], afr[mt][2], afr[mt][3],
                        smem_u32(&As[cur][wm + mt * 16 + (lane & 15)][k16 + (lane >> 4) * 8]));
#pragma unroll
            for (int g = 0; g < 2; ++g) {
                uint32_t b0, b1, b2, b3;
                ldsm_x4(b0, b1, b2, b3,
                        smem_u32(&Bs[cur][wn + g * 16 + (lane & 15)][k16 + (lane >> 4) * 8]));
                bfr[2 * g][0] = b0;     bfr[2 * g][1] = b2;
                bfr[2 * g + 1][0] = b1; bfr[2 * g + 1][1] = b3;
            }
#pragma unroll
            for (int mt = 0; mt < MT; ++mt)
#pragma unroll
                for (int nt = 0; nt < 4; ++nt)
                    mma_f16(acc[mt][nt], afr[mt], bfr[nt]);
        }

        if (ch < 15) {
#pragma unroll
            for (int it = 0; it < MT; ++it) {
                float4 v = pa[it];
                *(uint2*)&As[nxt][am + it * 32][akq * 4] =
                    make_uint2(pack_half2(v.x, v.y), pack_half2(v.z, v.w));
            }
#pragma unroll
            for (int it = 0; it < 2; ++it)
                *(uint4*)&Bs[nxt][bn_r + it * 64][bseg * 8] = pb[it];
        }
        __syncthreads();
    }

    const int r = lane >> 2, c = lane & 3;
#pragma unroll
    for (int mt = 0; mt < MT; ++mt) {
#pragma unroll
        for (int nt = 0; nt < 4; ++nt) {
            int row0 = bm + wm + mt * 16 + r;
            int col  = bn + wn + nt * 8 + 2 * c;
            if (HALF_OUT) {
                __half* C = (__half*)Cv;
                *(__half2*)&C[(size_t)row0 * 512 + col] =
                    __floats2half2_rn(acc[mt][nt][0], acc[mt][nt][1]);
                *(__half2*)&C[(size_t)(row0 + 8) * 512 + col] =
                    __floats2half2_rn(acc[mt][nt][2], acc[mt][nt][3]);
            } else {
                float* C = (float*)Cv;
                *(float2*)&C[(size_t)row0 * 512 + col] =
                    make_float2(acc[mt][nt][0], acc[mt][nt][1]);
                *(float2*)&C[(size_t)(row0 + 8) * 512 + col] =
                    make_float2(acc[mt][nt][2], acc[mt][nt][3]);
            }
        }
    }
}

__global__ __launch_bounds__(256) void qkv_gemm_kernel(
        const float* __restrict__ states, const float* __restrict__ key_states) {
    const float* A; const __half* Bt; __half* C;
    if (blockIdx.z == 0)      { A = states;     Bt = g_wqt; C = g_qh; }
    else if (blockIdx.z == 1) { A = key_states; Bt = g_wkt; C = g_kh; }
    else                      { A = key_states; Bt = g_wvt; C = g_vh; }
    gemm_body<4, true>(A, Bt, C, blockIdx.x * 128, blockIdx.y * 128);
}

// 64-row tiles -> 256 blocks (fills the chip; 128-block version left a
// single under-filled wave)
__global__ __launch_bounds__(256) void out_gemm_kernel(float* __restrict__ out) {
    gemm_body<2, false>(g_ctx, g_wot, out, blockIdx.x * 64, blockIdx.y * 128);
}

// -------------------- fused prep: weight transpose + bias scatter -----------
// blocks [0,1024): transpose+cvt the 4 weight matrices (32x32 tiles)
// blocks [1024,1152): bias table + scatter-add (bias_mat pre-zeroed)
__global__ __launch_bounds__(256) void prep_kernel(
        const float* __restrict__ wq, const float* __restrict__ wk,
        const float* __restrict__ wv, const float* __restrict__ wo,
        const int* __restrict__ ab, const float* __restrict__ embs,
        const float* __restrict__ scal, float* __restrict__ bias_mat) {
    const int bid = blockIdx.x;
    const int tid = threadIdx.x;
    if (bid < 1024) {
        const float* in; __half* out;
        switch (bid >> 8) {
            case 0:  in = wq; out = g_wqt; break;
            case 1:  in = wk; out = g_wkt; break;
            case 2:  in = wv; out = g_wvt; break;
            default: in = wo; out = g_wot; break;
        }
        __shared__ float t[32][33];
        int tx = tid & 31, ty = tid >> 5;
        int bx = (bid & 15) * 32, by = ((bid >> 4) & 15) * 32;
#pragma unroll
        for (int i = 0; i < 4; ++i)
            t[ty + 8 * i][tx] = in[(size_t)(by + ty + 8 * i) * D_ + bx + tx];
        __syncthreads();
#pragma unroll
        for (int i = 0; i < 4; ++i)
            out[(size_t)(bx + ty + 8 * i) * D_ + by + tx] =
                __float2half_rn(t[tx][ty + 8 * i]);
    } else {
        __shared__ float table[8];
        int e = tid >> 5, lane = tid & 31;
        {
            float s = embs[e * DH_ + lane] * scal[lane]
                    + embs[e * DH_ + 32 + lane] * scal[32 + lane];
#pragma unroll
            for (int off = 16; off; off >>= 1)
                s += __shfl_xor_sync(0xffffffffu, s, off);
            if (lane == 0) table[e] = s;
        }
        __syncthreads();
        int i = (bid - 1024) * 256 + tid;
        if (i < E_) {
            int et = ab[i * 4 + 0];
            int b  = ab[i * 4 + 1];
            int qi = ab[i * 4 + 2];
            int ki = ab[i * 4 + 3];
            atomicAdd(&bias_mat[((size_t)b * N_ + qi) * N_ + ki], table[et]);
        }
    }
}

// -------------------- fused causal attention: cp.async pipelined ------------
// flat grid 512 blocks (qt descending), 128 threads = 4 warps.
#define QP 72
__global__ __launch_bounds__(128) void attn_kernel(
        const float* __restrict__ bias_mat, float* __restrict__ ctx) {
    __shared__ __half Qs[64][QP];
    __shared__ __half Ks[2][64][QP];
    __shared__ __half Vs[2][64][QP];
    __shared__ float  bsk[64];

    const int bid = blockIdx.x;
    const int qt = 7 - (bid >> 6);
    const int h = (bid >> 3) & 7, b = bid & 7;
    const int tid = threadIdx.x, lane = tid & 31, warp = tid >> 5;
    const int r4 = lane >> 2, t4 = lane & 3;

    const int srow = tid >> 3, sseg = tid & 7;

    // prologue: async-stage K/V tile kt=0
#pragma unroll
    for (int it = 0; it < 4; ++it) {
        int row = srow + it * 16;
        size_t g = (size_t)(b * N_ + row) * D_ + h * DH_ + sseg * 8;
        cp16(smem_u32(&Ks[0][row][sseg * 8]), &g_kh[g]);
        cp16(smem_u32(&Vs[0][row][sseg * 8]), &g_vh[g]);
    }
    cp_commit();

    // stage Q tile
#pragma unroll
    for (int it = 0; it < 4; ++it) {
        int row = srow + it * 16;
        *(uint4*)&Qs[row][sseg * 8] =
            *(const uint4*)&g_qh[(size_t)(b * N_ + qt * 64 + row) * D_ + h * DH_ + sseg * 8];
    }
    __syncthreads();

    uint32_t qf[4][4];
    {
        int lrow = lane & 15, lcol = (lane >> 4) * 8;
#pragma unroll
        for (int ks = 0; ks < 4; ++ks)
            ldsm_x4(qf[ks][0], qf[ks][1], qf[ks][2], qf[ks][3],
                    smem_u32(&Qs[warp * 16 + lrow][ks * 16 + lcol]));
    }

    float m1 = -3.0e38f, m2 = -3.0e38f, l1 = 0.f, l2 = 0.f;
    float o[8][4];
#pragma unroll
    for (int dt = 0; dt < 8; ++dt)
#pragma unroll
        for (int i = 0; i < 4; ++i) o[dt][i] = 0.f;

    const int qg1 = qt * 64 + warp * 16 + r4;
    const int qg2 = qg1 + 8;
    const float* bp1 = bias_mat + (size_t)(b * N_ + qg1) * N_;
    const float* bp2 = bias_mat + (size_t)(b * N_ + qg2) * N_;

    for (int kt = 0; kt <= qt; ++kt) {
        const int cur = kt & 1;
        cp_wait0();
        __syncthreads();

        if (kt < qt) {
            const int nxt = cur ^ 1;
#pragma unroll
            for (int it = 0; it < 4; ++it) {
                int row = srow + it * 16;
                size_t g = (size_t)(b * N_ + (kt + 1) * 64 + row) * D_ + h * DH_ + sseg * 8;
                cp16(smem_u32(&Ks[nxt][row][sseg * 8]), &g_kh[g]);
                cp16(smem_u32(&Vs[nxt][row][sseg * 8]), &g_vh[g]);
            }
            cp_commit();
        }

        // summed_keys for this tile (2 threads per row, 32 halves each)
        {
            int rr = tid >> 1, hh = tid & 1;
            const uint4* p = (const uint4*)&Ks[cur][rr][hh * 32];
            float s = 0.f;
#pragma unroll
            for (int i = 0; i < 4; ++i) {
                uint4 v = p[i];
                const __half2* hp = (const __half2*)&v;
#pragma unroll
                for (int j = 0; j < 4; ++j) {
                    float2 f = __half22float2(hp[j]);
                    s += f.x + f.y;
                }
            }
            s += __shfl_xor_sync(0xffffffffu, s, 1);
            if (!hh) bsk[rr] = s;
        }
        __syncthreads();

        float s[8][4];
#pragma unroll
        for (int nt = 0; nt < 8; ++nt) {
#pragma unroll
            for (int i = 0; i < 4; ++i) s[nt][i] = 0.f;
#pragma unroll
            for (int ks = 0; ks < 4; ++ks) {
                uint32_t bf[2];
                ldsm_x2(bf[0], bf[1],
                        smem_u32(&Ks[cur][nt * 8 + (lane & 7)][ks * 16 + ((lane >> 3) & 1) * 8]));
                mma_f16(s[nt], qf[ks], bf);
            }
        }

        float tm1 = -3.0e38f, tm2 = -3.0e38f;
#pragma unroll
        for (int nt = 0; nt < 8; ++nt) {
            int kl = nt * 8 + 2 * t4;
            int kg = kt * 64 + kl;
            float2 bv1 = *(const float2*)&bp1[kg];
            float2 bv2 = *(const float2*)&bp2[kg];
            float s0 = bsk[kl], s1 = bsk[kl + 1];
            s[nt][0] = (kg     <= qg1) ? (s[nt][0] + bv1.x * s0) * 0.125f : -3.0e38f;
            s[nt][1] = (kg + 1 <= qg1) ? (s[nt][1] + bv1.y * s1) * 0.125f : -3.0e38f;
            s[nt][2] = (kg     <= qg2) ? (s[nt][2] + bv2.x * s0) * 0.125f : -3.0e38f;
            s[nt][3] = (kg + 1 <= qg2) ? (s[nt][3] + bv2.y * s1) * 0.125f : -3.0e38f;
            tm1 = fmaxf(tm1, fmaxf(s[nt][0], s[nt][1]));
            tm2 = fmaxf(tm2, fmaxf(s[nt][2], s[nt][3]));
        }
        tm1 = fmaxf(tm1, __shfl_xor_sync(0xffffffffu, tm1, 1));
        tm1 = fmaxf(tm1, __shfl_xor_sync(0xffffffffu, tm1, 2));
        tm2 = fmaxf(tm2, __shfl_xor_sync(0xffffffffu, tm2, 1));
        tm2 = fmaxf(tm2, __shfl_xor_sync(0xffffffffu, tm2, 2));

        float mn1 = fmaxf(m1, tm1), mn2 = fmaxf(m2, tm2);
        float c1 = __expf(m1 - mn1), c2 = __expf(m2 - mn2);
        float sum1 = 0.f, sum2 = 0.f;
#pragma unroll
        for (int nt = 0; nt < 8; ++nt) {
            s[nt][0] = __expf(s[nt][0] - mn1);
            s[nt][1] = __expf(s[nt][1] - mn1);
            s[nt][2] = __expf(s[nt][2] - mn2);
            s[nt][3] = __expf(s[nt][3] - mn2);
            sum1 += s[nt][0] + s[nt][1];
            sum2 += s[nt][2] + s[nt][3];
        }
        sum1 += __shfl_xor_sync(0xffffffffu, sum1, 1);
        sum1 += __shfl_xor_sync(0xffffffffu, sum1, 2);
        sum2 += __shfl_xor_sync(0xffffffffu, sum2, 1);
        sum2 += __shfl_xor_sync(0xffffffffu, sum2, 2);
        l1 = l1 * c1 + sum1; m1 = mn1;
        l2 = l2 * c2 + sum2; m2 = mn2;
#pragma unroll
        for (int dt = 0; dt < 8; ++dt) {
            o[dt][0] *= c1; o[dt][1] *= c1;
            o[dt][2] *= c2; o[dt][3] *= c2;
        }

        uint32_t pf[4][4];
#pragma unroll
        for (int kst = 0; kst < 4; ++kst) {
            pf[kst][0] = pack_half2(s[2 * kst][0],     s[2 * kst][1]);
            pf[kst][1] = pack_half2(s[2 * kst][2],     s[2 * kst][3]);
            pf[kst][2] = pack_half2(s[2 * kst + 1][0], s[2 * kst + 1][1]);
            pf[kst][3] = pack_half2(s[2 * kst + 1][2], s[2 * kst + 1][3]);
        }

#pragma unroll
        for (int g = 0; g < 4; ++g) {
#pragma unroll
            for (int kst = 0; kst < 4; ++kst) {
                uint32_t b0, b1, b2, b3;
                ldsm_x4t(b0, b1, b2, b3,
                         smem_u32(&Vs[cur][kst * 16 + (lane & 15)][g * 16 + (lane >> 4) * 8]));
                uint32_t bfa[2] = {b0, b1}, bfb[2] = {b2, b3};
                mma_f16(o[2 * g],     pf[kst], bfa);
                mma_f16(o[2 * g + 1], pf[kst], bfb);
            }
        }
    }

    float inv1 = 1.0f / l1, inv2 = 1.0f / l2;
#pragma unroll
    for (int dt = 0; dt < 8; ++dt) {
        int col = h * DH_ + dt * 8 + 2 * t4;
        *(float2*)&ctx[(size_t)(b * N_ + qg1) * D_ + col] =
            make_float2(o[dt][0] * inv1, o[dt][1] * inv1);
        *(float2*)&ctx[(size_t)(b * N_ + qg2) * D_ + col] =
            make_float2(o[dt][2] * inv2, o[dt][3] * inv2);
    }
}

// -------------------- launch -------------------------------------------------
extern "C" void kernel_launch(void* const* d_in, const int* in_sizes, int n_in,
                              void* d_out, int out_size) {
    const float* states     = (const float*)d_in[0];
    const float* key_states = (const float*)d_in[1];
    const int*   ab         = (const int*)d_in[3];
    const float* Wq         = (const float*)d_in[4];
    const float* Wk         = (const float*)d_in[5];
    const float* Wv         = (const float*)d_in[6];
    const float* Wo         = (const float*)d_in[7];
    const float* bias_embs  = (const float*)d_in[8];
    const float* bias_scal  = (const float*)d_in[9];
    float* out = (float*)d_out;

    float *gbias, *gctx;
    cudaGetSymbolAddress((void**)&gbias, g_bias);
    cudaGetSymbolAddress((void**)&gctx,  g_ctx);

    cudaMemsetAsync(gbias, 0, sizeof(float) * B_ * N_ * N_, 0);

    // fused: weight transpose+cvt (1024 blocks) + bias scatter (128 blocks)
    prep_kernel<<<1152, 256>>>(Wq, Wk, Wv, Wo, ab, bias_embs, bias_scal, gbias);

    // QKV projections
    dim3 qkvgrid(BN_ / 128, D_ / 128, 3);
    qkv_gemm_kernel<<<qkvgrid, 256>>>(states, key_states);

    attn_kernel<<<512, 128>>>(gbias, gctx);

    dim3 ogrid(BN_ / 64, D_ / 128);   // 256 blocks
    out_gemm_kernel<<<ogrid, 256>>>(out);
}

// round 14
// speedup vs baseline: 1.0254x; 1.0254x over previous
#include <cuda_runtime.h>
#include <cuda_fp16.h>
#include <cstdint>
#include <math.h>

#define B_  8
#define N_  512
#define D_  512
#define H_  8
#define DH_ 64
#define E_  32768
#define BN_ (B_ * N_)          // 4096 rows

// -------------------- scratch (device globals) -----------------------------
__device__ __half g_sh[BN_ * D_];    // states fp16
__device__ __half g_kih[BN_ * D_];   // key_states fp16
__device__ __half g_qh[BN_ * D_];
__device__ __half g_kh[BN_ * D_];
__device__ __half g_vh[BN_ * D_];
__device__ __half g_ctxh[BN_ * D_];  // context fp16
__device__ float  g_bias[B_ * N_ * N_];
__device__ __half g_wqt[D_ * D_];    // W^T fp16, [n][k]
__device__ __half g_wkt[D_ * D_];
__device__ __half g_wvt[D_ * D_];
__device__ __half g_wot[D_ * D_];

// -------------------- helpers ----------------------------------------------
__device__ __forceinline__ uint32_t smem_u32(const void* p) {
    uint32_t a;
    asm("{ .reg .u64 t; cvta.to.shared.u64 t, %1; cvt.u32.u64 %0, t; }"
        : "=r"(a) : "l"(p));
    return a;
}
__device__ __forceinline__ uint32_t pack_half2(float x, float y) {
    __half2 h = __floats2half2_rn(x, y);
    return *(uint32_t*)&h;
}
__device__ __forceinline__ void mma_f16(float* d, const uint32_t* a, const uint32_t* b) {
    asm volatile(
        "mma.sync.aligned.m16n8k16.row.col.f32.f16.f16.f32 "
        "{%0,%1,%2,%3}, {%4,%5,%6,%7}, {%8,%9}, {%0,%1,%2,%3};\n"
        : "+f"(d[0]), "+f"(d[1]), "+f"(d[2]), "+f"(d[3])
        : "r"(a[0]), "r"(a[1]), "r"(a[2]), "r"(a[3]), "r"(b[0]), "r"(b[1]));
}
__device__ __forceinline__ void ldsm_x4(uint32_t& r0, uint32_t& r1,
                                        uint32_t& r2, uint32_t& r3, uint32_t a) {
    asm volatile("ldmatrix.sync.aligned.m8n8.x4.shared.b16 {%0,%1,%2,%3}, [%4];"
                 : "=r"(r0), "=r"(r1), "=r"(r2), "=r"(r3) : "r"(a));
}
__device__ __forceinline__ void ldsm_x2(uint32_t& r0, uint32_t& r1, uint32_t a) {
    asm volatile("ldmatrix.sync.aligned.m8n8.x2.shared.b16 {%0,%1}, [%2];"
                 : "=r"(r0), "=r"(r1) : "r"(a));
}
__device__ __forceinline__ void ldsm_x4t(uint32_t& r0, uint32_t& r1,
                                         uint32_t& r2, uint32_t& r3, uint32_t a) {
    asm volatile("ldmatrix.sync.aligned.m8n8.x4.trans.shared.b16 {%0,%1,%2,%3}, [%4];"
                 : "=r"(r0), "=r"(r1), "=r"(r2), "=r"(r3) : "r"(a));
}
__device__ __forceinline__ void cp16(uint32_t s, const void* g) {
    asm volatile("cp.async.cg.shared.global [%0], [%1], 16;" :: "r"(s), "l"(g));
}
__device__ __forceinline__ void cp_commit() {
    asm volatile("cp.async.commit_group;" ::: "memory");
}
__device__ __forceinline__ void cp_wait0() {
    asm volatile("cp.async.wait_group 0;" ::: "memory");
}

// -------------------- fp16 GEMM, cp.async double-buffered -------------------
// C = A[4096,512] * Bt^T (all fp16 gmem). Tile 32*MT x 128, KB=32,
// 256 threads = 8 warps (2m x 4n). One __syncthreads per K-chunk.
#define GP 40
template <int MT, bool HALF_OUT>
__device__ __forceinline__ void gemm_body(const __half* __restrict__ A,
                                          const __half* __restrict__ Bt,
                                          void* __restrict__ Cv,
                                          int bm, int bn) {
    __shared__ __half As[2][32 * MT][GP];
    __shared__ __half Bs[2][128][GP];

    const int tid  = threadIdx.x;
    const int lane = tid & 31;
    const int wid  = tid >> 5;
    const int wm   = (wid & 1) * (16 * MT);
    const int wn   = (wid >> 1) * 32;

    float acc[MT][4][4];
#pragma unroll
    for (int mt = 0; mt < MT; ++mt)
#pragma unroll
        for (int nt = 0; nt < 4; ++nt)
#pragma unroll
            for (int i = 0; i < 4; ++i) acc[mt][nt][i] = 0.f;

    // stage chunk 0
#pragma unroll
    for (int it = 0; it < MT / 2; ++it) {
        int idx = tid + it * 256;
        int row = idx >> 2, c4 = idx & 3;
        cp16(smem_u32(&As[0][row][c4 * 8]), &A[(size_t)(bm + row) * 512 + c4 * 8]);
    }
#pragma unroll
    for (int it = 0; it < 2; ++it) {
        int idx = tid + it * 256;
        int row = idx >> 2, c4 = idx & 3;
        cp16(smem_u32(&Bs[0][row][c4 * 8]), &Bt[(size_t)(bn + row) * 512 + c4 * 8]);
    }
    cp_commit();

#pragma unroll 2
    for (int ch = 0; ch < 16; ++ch) {
        const int cur = ch & 1;
        cp_wait0();
        __syncthreads();

        if (ch < 15) {
            const int nxt = cur ^ 1;
            const int k0 = (ch + 1) * 32;
#pragma unroll
            for (int it = 0; it < MT / 2; ++it) {
                int idx = tid + it * 256;
                int row = idx >> 2, c4 = idx & 3;
                cp16(smem_u32(&As[nxt][row][c4 * 8]),
                     &A[(size_t)(bm + row) * 512 + k0 + c4 * 8]);
            }
#pragma unroll
            for (int it = 0; it < 2; ++it) {
                int idx = tid + it * 256;
                int row = idx >> 2, c4 = idx & 3;
                cp16(smem_u32(&Bs[nxt][row][c4 * 8]),
                     &Bt[(size_t)(bn + row) * 512 + k0 + c4 * 8]);
            }
            cp_commit();
        }

#pragma unroll
        for (int ks = 0; ks < 2; ++ks) {
            const int k16 = ks * 16;
            uint32_t afr[MT][4], bfr[4][2];
#pragma unroll
            for (int mt = 0; mt < MT; ++mt)
                ldsm_x4(afr[mt][0], afr[mt][1], afr[mt][2], afr[mt][3],
                        smem_u32(&As[cur][wm + mt * 16 + (lane & 15)][k16 + (lane >> 4) * 8]));
#pragma unroll
            for (int g = 0; g < 2; ++g) {
                uint32_t b0, b1, b2, b3;
                ldsm_x4(b0, b1, b2, b3,
                        smem_u32(&Bs[cur][wn + g * 16 + (lane & 15)][k16 + (lane >> 4) * 8]));
                bfr[2 * g][0] = b0;     bfr[2 * g][1] = b2;
                bfr[2 * g + 1][0] = b1; bfr[2 * g + 1][1] = b3;
            }
#pragma unroll
            for (int mt = 0; mt < MT; ++mt)
#pragma unroll
                for (int nt = 0; nt < 4; ++nt)
                    mma_f16(acc[mt][nt], afr[mt], bfr[nt]);
        }
    }

    const int r = lane >> 2, c = lane & 3;
#pragma unroll
    for (int mt = 0; mt < MT; ++mt) {
#pragma unroll
        for (int nt = 0; nt < 4; ++nt) {
            int row0 = bm + wm + mt * 16 + r;
            int col  = bn + wn + nt * 8 + 2 * c;
            if (HALF_OUT) {
                __half* C = (__half*)Cv;
                *(__half2*)&C[(size_t)row0 * 512 + col] =
                    __floats2half2_rn(acc[mt][nt][0], acc[mt][nt][1]);
                *(__half2*)&C[(size_t)(row0 + 8) * 512 + col] =
                    __floats2half2_rn(acc[mt][nt][2], acc[mt][nt][3]);
            } else {
                float* C = (float*)Cv;
                *(float2*)&C[(size_t)row0 * 512 + col] =
                    make_float2(acc[mt][nt][0], acc[mt][nt][1]);
                *(float2*)&C[(size_t)(row0 + 8) * 512 + col] =
                    make_float2(acc[mt][nt][2], acc[mt][nt][3]);
            }
        }
    }
}

__global__ __launch_bounds__(256) void qkv_gemm_kernel() {
    const __half* A; const __half* Bt; __half* C;
    if (blockIdx.z == 0)      { A = g_sh;  Bt = g_wqt; C = g_qh; }
    else if (blockIdx.z == 1) { A = g_kih; Bt = g_wkt; C = g_kh; }
    else                      { A = g_kih; Bt = g_wvt; C = g_vh; }
    gemm_body<4, true>(A, Bt, C, blockIdx.x * 128, blockIdx.y * 128);
}

__global__ __launch_bounds__(256) void out_gemm_kernel(float* __restrict__ out) {
    gemm_body<2, false>(g_ctxh, g_wot, out, blockIdx.x * 64, blockIdx.y * 128);
}

// -------------------- fused prep: transpose + scatter + input cvt -----------
// [0,1024): weight transpose+cvt; [1024,1152): bias scatter;
// [1152,3200): states/key_states fp32->fp16 (2048 elems per block)
__global__ __launch_bounds__(256) void prep_kernel(
        const float* __restrict__ wq, const float* __restrict__ wk,
        const float* __restrict__ wv, const float* __restrict__ wo,
        const int* __restrict__ ab, const float* __restrict__ embs,
        const float* __restrict__ scal, float* __restrict__ bias_mat,
        const float* __restrict__ states, const float* __restrict__ key_states) {
    const int bid = blockIdx.x;
    const int tid = threadIdx.x;
    if (bid < 1024) {
        const float* in; __half* out;
        switch (bid >> 8) {
            case 0:  in = wq; out = g_wqt; break;
            case 1:  in = wk; out = g_wkt; break;
            case 2:  in = wv; out = g_wvt; break;
            default: in = wo; out = g_wot; break;
        }
        __shared__ float t[32][33];
        int tx = tid & 31, ty = tid >> 5;
        int bx = (bid & 15) * 32, by = ((bid >> 4) & 15) * 32;
#pragma unroll
        for (int i = 0; i < 4; ++i)
            t[ty + 8 * i][tx] = in[(size_t)(by + ty + 8 * i) * D_ + bx + tx];
        __syncthreads();
#pragma unroll
        for (int i = 0; i < 4; ++i)
            out[(size_t)(bx + ty + 8 * i) * D_ + by + tx] =
                __float2half_rn(t[tx][ty + 8 * i]);
    } else if (bid < 1152) {
        __shared__ float table[8];
        int e = tid >> 5, lane = tid & 31;
        {
            float s = embs[e * DH_ + lane] * scal[lane]
                    + embs[e * DH_ + 32 + lane] * scal[32 + lane];
#pragma unroll
            for (int off = 16; off; off >>= 1)
                s += __shfl_xor_sync(0xffffffffu, s, off);
            if (lane == 0) table[e] = s;
        }
        __syncthreads();
        int i = (bid - 1024) * 256 + tid;
        if (i < E_) {
            int et = ab[i * 4 + 0];
            int b  = ab[i * 4 + 1];
            int qi = ab[i * 4 + 2];
            int ki = ab[i * 4 + 3];
            atomicAdd(&bias_mat[((size_t)b * N_ + qi) * N_ + ki], table[et]);
        }
    } else {
        int c = bid - 1152;                 // 2048 blocks
        const float* in = (c >> 10) ? key_states : states;
        __half* out     = (c >> 10) ? g_kih : g_sh;
        size_t base = (size_t)(c & 1023) * 2048 + tid * 8;
        float4 v0 = *(const float4*)&in[base];
        float4 v1 = *(const float4*)&in[base + 4];
        uint4 w = make_uint4(pack_half2(v0.x, v0.y), pack_half2(v0.z, v0.w),
                             pack_half2(v1.x, v1.y), pack_half2(v1.z, v1.w));
        *(uint4*)&out[base] = w;
    }
}

// -------------------- fused causal attention: cp.async pipelined ------------
#define QP 72
__global__ __launch_bounds__(128) void attn_kernel(
        const float* __restrict__ bias_mat) {
    __shared__ __half Qs[64][QP];
    __shared__ __half Ks[2][64][QP];
    __shared__ __half Vs[2][64][QP];
    __shared__ float  bsk[64];

    const int bid = blockIdx.x;
    const int qt = 7 - (bid >> 6);
    const int h = (bid >> 3) & 7, b = bid & 7;
    const int tid = threadIdx.x, lane = tid & 31, warp = tid >> 5;
    const int r4 = lane >> 2, t4 = lane & 3;

    const int srow = tid >> 3, sseg = tid & 7;

#pragma unroll
    for (int it = 0; it < 4; ++it) {
        int row = srow + it * 16;
        size_t g = (size_t)(b * N_ + row) * D_ + h * DH_ + sseg * 8;
        cp16(smem_u32(&Ks[0][row][sseg * 8]), &g_kh[g]);
        cp16(smem_u32(&Vs[0][row][sseg * 8]), &g_vh[g]);
    }
    cp_commit();

#pragma unroll
    for (int it = 0; it < 4; ++it) {
        int row = srow + it * 16;
        *(uint4*)&Qs[row][sseg * 8] =
            *(const uint4*)&g_qh[(size_t)(b * N_ + qt * 64 + row) * D_ + h * DH_ + sseg * 8];
    }
    __syncthreads();

    uint32_t qf[4][4];
    {
        int lrow = lane & 15, lcol = (lane >> 4) * 8;
#pragma unroll
        for (int ks = 0; ks < 4; ++ks)
            ldsm_x4(qf[ks][0], qf[ks][1], qf[ks][2], qf[ks][3],
                    smem_u32(&Qs[warp * 16 + lrow][ks * 16 + lcol]));
    }

    float m1 = -3.0e38f, m2 = -3.0e38f, l1 = 0.f, l2 = 0.f;
    float o[8][4];
#pragma unroll
    for (int dt = 0; dt < 8; ++dt)
#pragma unroll
        for (int i = 0; i < 4; ++i) o[dt][i] = 0.f;

    const int qg1 = qt * 64 + warp * 16 + r4;
    const int qg2 = qg1 + 8;
    const float* bp1 = bias_mat + (size_t)(b * N_ + qg1) * N_;
    const float* bp2 = bias_mat + (size_t)(b * N_ + qg2) * N_;

    for (int kt = 0; kt <= qt; ++kt) {
        const int cur = kt & 1;
        cp_wait0();
        __syncthreads();

        if (kt < qt) {
            const int nxt = cur ^ 1;
#pragma unroll
            for (int it = 0; it < 4; ++it) {
                int row = srow + it * 16;
                size_t g = (size_t)(b * N_ + (kt + 1) * 64 + row) * D_ + h * DH_ + sseg * 8;
                cp16(smem_u32(&Ks[nxt][row][sseg * 8]), &g_kh[g]);
                cp16(smem_u32(&Vs[nxt][row][sseg * 8]), &g_vh[g]);
            }
            cp_commit();
        }

        {
            int rr = tid >> 1, hh = tid & 1;
            const uint4* p = (const uint4*)&Ks[cur][rr][hh * 32];
            float s = 0.f;
#pragma unroll
            for (int i = 0; i < 4; ++i) {
                uint4 v = p[i];
                const __half2* hp = (const __half2*)&v;
#pragma unroll
                for (int j = 0; j < 4; ++j) {
                    float2 f = __half22float2(hp[j]);
                    s += f.x + f.y;
                }
            }
            s += __shfl_xor_sync(0xffffffffu, s, 1);
            if (!hh) bsk[rr] = s;
        }
        __syncthreads();

        float s[8][4];
#pragma unroll
        for (int nt = 0; nt < 8; ++nt) {
#pragma unroll
            for (int i = 0; i < 4; ++i) s[nt][i] = 0.f;
#pragma unroll
            for (int ks = 0; ks < 4; ++ks) {
                uint32_t bf[2];
                ldsm_x2(bf[0], bf[1],
                        smem_u32(&Ks[cur][nt * 8 + (lane & 7)][ks * 16 + ((lane >> 3) & 1) * 8]));
                mma_f16(s[nt], qf[ks], bf);
            }
        }

        float tm1 = -3.0e38f, tm2 = -3.0e38f;
#pragma unroll
        for (int nt = 0; nt < 8; ++nt) {
            int kl = nt * 8 + 2 * t4;
            int kg = kt * 64 + kl;
            float2 bv1 = *(const float2*)&bp1[kg];
            float2 bv2 = *(const float2*)&bp2[kg];
            float s0 = bsk[kl], s1 = bsk[kl + 1];
            s[nt][0] = (kg     <= qg1) ? (s[nt][0] + bv1.x * s0) * 0.125f : -3.0e38f;
            s[nt][1] = (kg + 1 <= qg1) ? (s[nt][1] + bv1.y * s1) * 0.125f : -3.0e38f;
            s[nt][2] = (kg     <= qg2) ? (s[nt][2] + bv2.x * s0) * 0.125f : -3.0e38f;
            s[nt][3] = (kg + 1 <= qg2) ? (s[nt][3] + bv2.y * s1) * 0.125f : -3.0e38f;
            tm1 = fmaxf(tm1, fmaxf(s[nt][0], s[nt][1]));
            tm2 = fmaxf(tm2, fmaxf(s[nt][2], s[nt][3]));
        }
        tm1 = fmaxf(tm1, __shfl_xor_sync(0xffffffffu, tm1, 1));
        tm1 = fmaxf(tm1, __shfl_xor_sync(0xffffffffu, tm1, 2));
        tm2 = fmaxf(tm2, __shfl_xor_sync(0xffffffffu, tm2, 1));
        tm2 = fmaxf(tm2, __shfl_xor_sync(0xffffffffu, tm2, 2));

        float mn1 = fmaxf(m1, tm1), mn2 = fmaxf(m2, tm2);
        float c1 = __expf(m1 - mn1), c2 = __expf(m2 - mn2);
        float sum1 = 0.f, sum2 = 0.f;
#pragma unroll
        for (int nt = 0; nt < 8; ++nt) {
            s[nt][0] = __expf(s[nt][0] - mn1);
            s[nt][1] = __expf(s[nt][1] - mn1);
            s[nt][2] = __expf(s[nt][2] - mn2);
            s[nt][3] = __expf(s[nt][3] - mn2);
            sum1 += s[nt][0] + s[nt][1];
            sum2 += s[nt][2] + s[nt][3];
        }
        sum1 += __shfl_xor_sync(0xffffffffu, sum1, 1);
        sum1 += __shfl_xor_sync(0xffffffffu, sum1, 2);
        sum2 += __shfl_xor_sync(0xffffffffu, sum2, 1);
        sum2 += __shfl_xor_sync(0xffffffffu, sum2, 2);
        l1 = l1 * c1 + sum1; m1 = mn1;
        l2 = l2 * c2 + sum2; m2 = mn2;
#pragma unroll
        for (int dt = 0; dt < 8; ++dt) {
            o[dt][0] *= c1; o[dt][1] *= c1;
            o[dt][2] *= c2; o[dt][3] *= c2;
        }

        uint32_t pf[4][4];
#pragma unroll
        for (int kst = 0; kst < 4; ++kst) {
            pf[kst][0] = pack_half2(s[2 * kst][0],     s[2 * kst][1]);
            pf[kst][1] = pack_half2(s[2 * kst][2],     s[2 * kst][3]);
            pf[kst][2] = pack_half2(s[2 * kst + 1][0], s[2 * kst + 1][1]);
            pf[kst][3] = pack_half2(s[2 * kst + 1][2], s[2 * kst + 1][3]);
        }

#pragma unroll
        for (int g = 0; g < 4; ++g) {
#pragma unroll
            for (int kst = 0; kst < 4; ++kst) {
                uint32_t b0, b1, b2, b3;
                ldsm_x4t(b0, b1, b2, b3,
                         smem_u32(&Vs[cur][kst * 16 + (lane & 15)][g * 16 + (lane >> 4) * 8]));
                uint32_t bfa[2] = {b0, b1}, bfb[2] = {b2, b3};
                mma_f16(o[2 * g],     pf[kst], bfa);
                mma_f16(o[2 * g + 1], pf[kst], bfb);
            }
        }
    }

    // normalize + write context fp16
    float inv1 = 1.0f / l1, inv2 = 1.0f / l2;
#pragma unroll
    for (int dt = 0; dt < 8; ++dt) {
        int col = h * DH_ + dt * 8 + 2 * t4;
        *(__half2*)&g_ctxh[(size_t)(b * N_ + qg1) * D_ + col] =
            __floats2half2_rn(o[dt][0] * inv1, o[dt][1] * inv1);
        *(__half2*)&g_ctxh[(size_t)(b * N_ + qg2) * D_ + col] =
            __floats2half2_rn(o[dt][2] * inv2, o[dt][3] * inv2);
    }
}

// -------------------- launch -------------------------------------------------
extern "C" void kernel_launch(void* const* d_in, const int* in_sizes, int n_in,
                              void* d_out, int out_size) {
    const float* states     = (const float*)d_in[0];
    const float* key_states = (const float*)d_in[1];
    const int*   ab         = (const int*)d_in[3];
    const float* Wq         = (const float*)d_in[4];
    const float* Wk         = (const float*)d_in[5];
    const float* Wv         = (const float*)d_in[6];
    const float* Wo         = (const float*)d_in[7];
    const float* bias_embs  = (const float*)d_in[8];
    const float* bias_scal  = (const float*)d_in[9];
    float* out = (float*)d_out;

    float* gbias;
    cudaGetSymbolAddress((void**)&gbias, g_bias);

    cudaMemsetAsync(gbias, 0, sizeof(float) * B_ * N_ * N_, 0);

    // fused prep: weight transpose (1024) + bias scatter (128) + input cvt (2048)
    prep_kernel<<<3200, 256>>>(Wq, Wk, Wv, Wo, ab, bias_embs, bias_scal, gbias,
                               states, key_states);

    dim3 qkvgrid(BN_ / 128, D_ / 128, 3);
    qkv_gemm_kernel<<<qkvgrid, 256>>>();

    attn_kernel<<<512, 128>>>(gbias);

    dim3 ogrid(BN_ / 64, D_ / 128);   // 256 blocks
    out_gemm_kernel<<<ogrid, 256>>>(out);
}

// round 15
// speedup vs baseline: 1.0526x; 1.0265x over previous
#include <cuda_runtime.h>
#include <cuda_fp16.h>
#include <cstdint>
#include <math.h>

#define B_  8
#define N_  512
#define D_  512
#define H_  8
#define DH_ 64
#define E_  32768
#define BN_ (B_ * N_)          // 4096 rows

// -------------------- scratch (device globals) -----------------------------
__device__ __half g_sh[BN_ * D_];    // states fp16
__device__ __half g_kih[BN_ * D_];   // key_states fp16
__device__ __half g_qh[BN_ * D_];
__device__ __half g_kh[BN_ * D_];
__device__ __half g_vh[BN_ * D_];
__device__ __half g_ctxh[BN_ * D_];  // context fp16
__device__ float  g_bias[B_ * N_ * N_];
__device__ float  g_sk[BN_ * H_];    // summed_keys
__device__ __half g_wqt[D_ * D_];    // W^T fp16, [n][k]
__device__ __half g_wkt[D_ * D_];
__device__ __half g_wvt[D_ * D_];
__device__ __half g_wot[D_ * D_];

// -------------------- helpers ----------------------------------------------
__device__ __forceinline__ uint32_t smem_u32(const void* p) {
    uint32_t a;
    asm("{ .reg .u64 t; cvta.to.shared.u64 t, %1; cvt.u32.u64 %0, t; }"
        : "=r"(a) : "l"(p));
    return a;
}
__device__ __forceinline__ uint32_t pack_half2(float x, float y) {
    __half2 h = __floats2half2_rn(x, y);
    return *(uint32_t*)&h;
}
__device__ __forceinline__ void mma_f16(float* d, const uint32_t* a, const uint32_t* b) {
    asm volatile(
        "mma.sync.aligned.m16n8k16.row.col.f32.f16.f16.f32 "
        "{%0,%1,%2,%3}, {%4,%5,%6,%7}, {%8,%9}, {%0,%1,%2,%3};\n"
        : "+f"(d[0]), "+f"(d[1]), "+f"(d[2]), "+f"(d[3])
        : "r"(a[0]), "r"(a[1]), "r"(a[2]), "r"(a[3]), "r"(b[0]), "r"(b[1]));
}
__device__ __forceinline__ void ldsm_x4(uint32_t& r0, uint32_t& r1,
                                        uint32_t& r2, uint32_t& r3, uint32_t a) {
    asm volatile("ldmatrix.sync.aligned.m8n8.x4.shared.b16 {%0,%1,%2,%3}, [%4];"
                 : "=r"(r0), "=r"(r1), "=r"(r2), "=r"(r3) : "r"(a));
}
__device__ __forceinline__ void ldsm_x2(uint32_t& r0, uint32_t& r1, uint32_t a) {
    asm volatile("ldmatrix.sync.aligned.m8n8.x2.shared.b16 {%0,%1}, [%2];"
                 : "=r"(r0), "=r"(r1) : "r"(a));
}
__device__ __forceinline__ void ldsm_x4t(uint32_t& r0, uint32_t& r1,
                                         uint32_t& r2, uint32_t& r3, uint32_t a) {
    asm volatile("ldmatrix.sync.aligned.m8n8.x4.trans.shared.b16 {%0,%1,%2,%3}, [%4];"
                 : "=r"(r0), "=r"(r1), "=r"(r2), "=r"(r3) : "r"(a));
}
__device__ __forceinline__ void cp16(uint32_t s, const void* g) {
    asm volatile("cp.async.cg.shared.global [%0], [%1], 16;" :: "r"(s), "l"(g));
}
__device__ __forceinline__ void cp_commit() {
    asm volatile("cp.async.commit_group;" ::: "memory");
}
__device__ __forceinline__ void cp_wait0() {
    asm volatile("cp.async.wait_group 0;" ::: "memory");
}
__device__ __forceinline__ void cp_wait1() {
    asm volatile("cp.async.wait_group 1;" ::: "memory");
}

// -------------------- fp16 GEMM, 3-stage cp.async pipeline ------------------
// C = A[4096,512] * Bt^T (all fp16 gmem). Tile 32*MT x 128, KB=32,
// 256 threads = 8 warps (2m x 4n). wait_group 1 => 2 chunks in flight.
#define GP 40
extern __shared__ char dynsmem[];

template <int MT, bool HALF_OUT>
__device__ __forceinline__ void gemm_body(const __half* __restrict__ A,
                                          const __half* __restrict__ Bt,
                                          void* __restrict__ Cv,
                                          int bm, int bn, bool doSk) {
    typedef __half ARow[GP];
    ARow (*As)[32 * MT] = (ARow(*)[32 * MT])dynsmem;                 // [3][32*MT][GP]
    ARow (*Bs)[128]     = (ARow(*)[128])(dynsmem + 3 * 32 * MT * GP * 2);

    const int tid  = threadIdx.x;
    const int lane = tid & 31;
    const int wid  = tid >> 5;
    const int wm   = (wid & 1) * (16 * MT);
    const int wn   = (wid >> 1) * 32;
    const int r = lane >> 2, c = lane & 3;

    float acc[MT][4][4];
#pragma unroll
    for (int mt = 0; mt < MT; ++mt)
#pragma unroll
        for (int nt = 0; nt < 4; ++nt)
#pragma unroll
            for (int i = 0; i < 4; ++i) acc[mt][nt][i] = 0.f;

    const int arow = tid >> 2, ac4 = tid & 3;

    // stage chunk into buffer s
    auto stage = [&](int s, int k0) {
#pragma unroll
        for (int it = 0; it < MT / 2; ++it) {
            int row = arow + it * 64;
            cp16(smem_u32(&As[s][row][ac4 * 8]),
                 &A[(size_t)(bm + row) * 512 + k0 + ac4 * 8]);
        }
#pragma unroll
        for (int it = 0; it < 2; ++it) {
            int row = arow + it * 64;
            cp16(smem_u32(&Bs[s][row][ac4 * 8]),
                 &Bt[(size_t)(bn + row) * 512 + k0 + ac4 * 8]);
        }
    };

    stage(0, 0);  cp_commit();
    stage(1, 32); cp_commit();

#pragma unroll
    for (int ch = 0; ch < 16; ++ch) {
        const int cur = ch % 3;
        cp_wait1();
        __syncthreads();

        if (ch + 2 < 16) stage((ch + 2) % 3, (ch + 2) * 32);
        cp_commit();

#pragma unroll
        for (int ks = 0; ks < 2; ++ks) {
            const int k16 = ks * 16;
            uint32_t afr[MT][4], bfr[4][2];
#pragma unroll
            for (int mt = 0; mt < MT; ++mt)
                ldsm_x4(afr[mt][0], afr[mt][1], afr[mt][2], afr[mt][3],
                        smem_u32(&As[cur][wm + mt * 16 + (lane & 15)][k16 + (lane >> 4) * 8]));
#pragma unroll
            for (int g = 0; g < 2; ++g) {
                uint32_t b0, b1, b2, b3;
                ldsm_x4(b0, b1, b2, b3,
                        smem_u32(&Bs[cur][wn + g * 16 + (lane & 15)][k16 + (lane >> 4) * 8]));
                bfr[2 * g][0] = b0;     bfr[2 * g][1] = b2;
                bfr[2 * g + 1][0] = b1; bfr[2 * g + 1][1] = b3;
            }
#pragma unroll
            for (int mt = 0; mt < MT; ++mt)
#pragma unroll
                for (int nt = 0; nt < 4; ++nt)
                    mma_f16(acc[mt][nt], afr[mt], bfr[nt]);
        }
    }

    // summed_keys epilogue (K projection only): warp's 32 cols lie in one head
    if (doSk) {
        int head = (bn + wn) >> 6;
#pragma unroll
        for (int mt = 0; mt < MT; ++mt) {
            float s0 = 0.f, s1 = 0.f;
#pragma unroll
            for (int nt = 0; nt < 4; ++nt) {
                s0 += acc[mt][nt][0] + acc[mt][nt][1];
                s1 += acc[mt][nt][2] + acc[mt][nt][3];
            }
            s0 += __shfl_xor_sync(0xffffffffu, s0, 1);
            s0 += __shfl_xor_sync(0xffffffffu, s0, 2);
            s1 += __shfl_xor_sync(0xffffffffu, s1, 1);
            s1 += __shfl_xor_sync(0xffffffffu, s1, 2);
            if (c == 0) {
                int row0 = bm + wm + mt * 16 + r;
                atomicAdd(&g_sk[(size_t)row0 * H_ + head], s0);
                atomicAdd(&g_sk[(size_t)(row0 + 8) * H_ + head], s1);
            }
        }
    }

#pragma unroll
    for (int mt = 0; mt < MT; ++mt) {
#pragma unroll
        for (int nt = 0; nt < 4; ++nt) {
            int row0 = bm + wm + mt * 16 + r;
            int col  = bn + wn + nt * 8 + 2 * c;
            if (HALF_OUT) {
                __half* C = (__half*)Cv;
                *(__half2*)&C[(size_t)row0 * 512 + col] =
                    __floats2half2_rn(acc[mt][nt][0], acc[mt][nt][1]);
                *(__half2*)&C[(size_t)(row0 + 8) * 512 + col] =
                    __floats2half2_rn(acc[mt][nt][2], acc[mt][nt][3]);
            } else {
                float* C = (float*)Cv;
                *(float2*)&C[(size_t)row0 * 512 + col] =
                    make_float2(acc[mt][nt][0], acc[mt][nt][1]);
                *(float2*)&C[(size_t)(row0 + 8) * 512 + col] =
                    make_float2(acc[mt][nt][2], acc[mt][nt][3]);
            }
        }
    }
}

#define SMEM_G(MT) (3 * (32 * (MT) * GP + 128 * GP) * 2)

__global__ __launch_bounds__(256) void qkv_gemm_kernel() {
    const __half* A; const __half* Bt; __half* C; bool doSk = false;
    if (blockIdx.z == 0)      { A = g_sh;  Bt = g_wqt; C = g_qh; }
    else if (blockIdx.z == 1) { A = g_kih; Bt = g_wkt; C = g_kh; doSk = true; }
    else                      { A = g_kih; Bt = g_wvt; C = g_vh; }
    gemm_body<4, true>(A, Bt, C, blockIdx.x * 128, blockIdx.y * 128, doSk);
}

__global__ __launch_bounds__(256) void out_gemm_kernel(float* __restrict__ out) {
    gemm_body<2, false>(g_ctxh, g_wot, out, blockIdx.x * 64, blockIdx.y * 128, false);
}

// -------------------- fused prep: transpose + scatter + input cvt -----------
__global__ __launch_bounds__(256) void prep_kernel(
        const float* __restrict__ wq, const float* __restrict__ wk,
        const float* __restrict__ wv, const float* __restrict__ wo,
        const int* __restrict__ ab, const float* __restrict__ embs,
        const float* __restrict__ scal, float* __restrict__ bias_mat,
        const float* __restrict__ states, const float* __restrict__ key_states) {
    const int bid = blockIdx.x;
    const int tid = threadIdx.x;
    if (bid < 1024) {
        const float* in; __half* out;
        switch (bid >> 8) {
            case 0:  in = wq; out = g_wqt; break;
            case 1:  in = wk; out = g_wkt; break;
            case 2:  in = wv; out = g_wvt; break;
            default: in = wo; out = g_wot; break;
        }
        __shared__ float t[32][33];
        int tx = tid & 31, ty = tid >> 5;
        int bx = (bid & 15) * 32, by = ((bid >> 4) & 15) * 32;
#pragma unroll
        for (int i = 0; i < 4; ++i)
            t[ty + 8 * i][tx] = in[(size_t)(by + ty + 8 * i) * D_ + bx + tx];
        __syncthreads();
#pragma unroll
        for (int i = 0; i < 4; ++i)
            out[(size_t)(bx + ty + 8 * i) * D_ + by + tx] =
                __float2half_rn(t[tx][ty + 8 * i]);
    } else if (bid < 1152) {
        __shared__ float table[8];
        int e = tid >> 5, lane = tid & 31;
        {
            float s = embs[e * DH_ + lane] * scal[lane]
                    + embs[e * DH_ + 32 + lane] * scal[32 + lane];
#pragma unroll
            for (int off = 16; off; off >>= 1)
                s += __shfl_xor_sync(0xffffffffu, s, off);
            if (lane == 0) table[e] = s;
        }
        __syncthreads();
        int i = (bid - 1024) * 256 + tid;
        if (i < E_) {
            int et = ab[i * 4 + 0];
            int b  = ab[i * 4 + 1];
            int qi = ab[i * 4 + 2];
            int ki = ab[i * 4 + 3];
            atomicAdd(&bias_mat[((size_t)b * N_ + qi) * N_ + ki], table[et]);
        }
    } else {
        int c = bid - 1152;                 // 2048 blocks
        const float* in = (c >> 10) ? key_states : states;
        __half* out     = (c >> 10) ? g_kih : g_sh;
        size_t base = (size_t)(c & 1023) * 2048 + tid * 8;
        float4 v0 = *(const float4*)&in[base];
        float4 v1 = *(const float4*)&in[base + 4];
        uint4 w = make_uint4(pack_half2(v0.x, v0.y), pack_half2(v0.z, v0.w),
                             pack_half2(v1.x, v1.y), pack_half2(v1.z, v1.w));
        *(uint4*)&out[base] = w;
    }
}

// -------------------- fused causal attention: cp.async, one sync/iter -------
#define QP 72
__global__ __launch_bounds__(128) void attn_kernel(
        const float* __restrict__ bias_mat) {
    __shared__ __half Qs[64][QP];
    __shared__ __half Ks[2][64][QP];
    __shared__ __half Vs[2][64][QP];

    const int bid = blockIdx.x;
    const int qt = 7 - (bid >> 6);
    const int h = (bid >> 3) & 7, b = bid & 7;
    const int tid = threadIdx.x, lane = tid & 31, warp = tid >> 5;
    const int r4 = lane >> 2, t4 = lane & 3;

    const int srow = tid >> 3, sseg = tid & 7;

#pragma unroll
    for (int it = 0; it < 4; ++it) {
        int row = srow + it * 16;
        size_t g = (size_t)(b * N_ + row) * D_ + h * DH_ + sseg * 8;
        cp16(smem_u32(&Ks[0][row][sseg * 8]), &g_kh[g]);
        cp16(smem_u32(&Vs[0][row][sseg * 8]), &g_vh[g]);
    }
    cp_commit();

#pragma unroll
    for (int it = 0; it < 4; ++it) {
        int row = srow + it * 16;
        *(uint4*)&Qs[row][sseg * 8] =
            *(const uint4*)&g_qh[(size_t)(b * N_ + qt * 64 + row) * D_ + h * DH_ + sseg * 8];
    }
    __syncthreads();

    uint32_t qf[4][4];
    {
        int lrow = lane & 15, lcol = (lane >> 4) * 8;
#pragma unroll
        for (int ks = 0; ks < 4; ++ks)
            ldsm_x4(qf[ks][0], qf[ks][1], qf[ks][2], qf[ks][3],
                    smem_u32(&Qs[warp * 16 + lrow][ks * 16 + lcol]));
    }

    float m1 = -3.0e38f, m2 = -3.0e38f, l1 = 0.f, l2 = 0.f;
    float o[8][4];
#pragma unroll
    for (int dt = 0; dt < 8; ++dt)
#pragma unroll
        for (int i = 0; i < 4; ++i) o[dt][i] = 0.f;

    const int qg1 = qt * 64 + warp * 16 + r4;
    const int qg2 = qg1 + 8;
    const float* bp1 = bias_mat + (size_t)(b * N_ + qg1) * N_;
    const float* bp2 = bias_mat + (size_t)(b * N_ + qg2) * N_;
    const float* skp = g_sk + (size_t)(b * N_) * H_ + h;

    for (int kt = 0; kt <= qt; ++kt) {
        const int cur = kt & 1;
        cp_wait0();
        __syncthreads();

        if (kt < qt) {
            const int nxt = cur ^ 1;
#pragma unroll
            for (int it = 0; it < 4; ++it) {
                int row = srow + it * 16;
                size_t g = (size_t)(b * N_ + (kt + 1) * 64 + row) * D_ + h * DH_ + sseg * 8;
                cp16(smem_u32(&Ks[nxt][row][sseg * 8]), &g_kh[g]);
                cp16(smem_u32(&Vs[nxt][row][sseg * 8]), &g_vh[g]);
            }
            cp_commit();
        }

        float s[8][4];
#pragma unroll
        for (int nt = 0; nt < 8; ++nt) {
#pragma unroll
            for (int i = 0; i < 4; ++i) s[nt][i] = 0.f;
#pragma unroll
            for (int ks = 0; ks < 4; ++ks) {
                uint32_t bf[2];
                ldsm_x2(bf[0], bf[1],
                        smem_u32(&Ks[cur][nt * 8 + (lane & 7)][ks * 16 + ((lane >> 3) & 1) * 8]));
                mma_f16(s[nt], qf[ks], bf);
            }
        }

        float tm1 = -3.0e38f, tm2 = -3.0e38f;
#pragma unroll
        for (int nt = 0; nt < 8; ++nt) {
            int kl = nt * 8 + 2 * t4;
            int kg = kt * 64 + kl;
            float2 bv1 = *(const float2*)&bp1[kg];
            float2 bv2 = *(const float2*)&bp2[kg];
            float s0 = skp[(size_t)kg * H_];
            float s1 = skp[(size_t)(kg + 1) * H_];
            s[nt][0] = (kg     <= qg1) ? (s[nt][0] + bv1.x * s0) * 0.125f : -3.0e38f;
            s[nt][1] = (kg + 1 <= qg1) ? (s[nt][1] + bv1.y * s1) * 0.125f : -3.0e38f;
            s[nt][2] = (kg     <= qg2) ? (s[nt][2] + bv2.x * s0) * 0.125f : -3.0e38f;
            s[nt][3] = (kg + 1 <= qg2) ? (s[nt][3] + bv2.y * s1) * 0.125f : -3.0e38f;
            tm1 = fmaxf(tm1, fmaxf(s[nt][0], s[nt][1]));
            tm2 = fmaxf(tm2, fmaxf(s[nt][2], s[nt][3]));
        }
        tm1 = fmaxf(tm1, __shfl_xor_sync(0xffffffffu, tm1, 1));
        tm1 = fmaxf(tm1, __shfl_xor_sync(0xffffffffu, tm1, 2));
        tm2 = fmaxf(tm2, __shfl_xor_sync(0xffffffffu, tm2, 1));
        tm2 = fmaxf(tm2, __shfl_xor_sync(0xffffffffu, tm2, 2));

        float mn1 = fmaxf(m1, tm1), mn2 = fmaxf(m2, tm2);
        float c1 = __expf(m1 - mn1), c2 = __expf(m2 - mn2);
        float sum1 = 0.f, sum2 = 0.f;
#pragma unroll
        for (int nt = 0; nt < 8; ++nt) {
            s[nt][0] = __expf(s[nt][0] - mn1);
            s[nt][1] = __expf(s[nt][1] - mn1);
            s[nt][2] = __expf(s[nt][2] - mn2);
            s[nt][3] = __expf(s[nt][3] - mn2);
            sum1 += s[nt][0] + s[nt][1];
            sum2 += s[nt][2] + s[nt][3];
        }
        sum1 += __shfl_xor_sync(0xffffffffu, sum1, 1);
        sum1 += __shfl_xor_sync(0xffffffffu, sum1, 2);
        sum2 += __shfl_xor_sync(0xffffffffu, sum2, 1);
        sum2 += __shfl_xor_sync(0xffffffffu, sum2, 2);
        l1 = l1 * c1 + sum1; m1 = mn1;
        l2 = l2 * c2 + sum2; m2 = mn2;
#pragma unroll
        for (int dt = 0; dt < 8; ++dt) {
            o[dt][0] *= c1; o[dt][1] *= c1;
            o[dt][2] *= c2; o[dt][3] *= c2;
        }

        uint32_t pf[4][4];
#pragma unroll
        for (int kst = 0; kst < 4; ++kst) {
            pf[kst][0] = pack_half2(s[2 * kst][0],     s[2 * kst][1]);
            pf[kst][1] = pack_half2(s[2 * kst][2],     s[2 * kst][3]);
            pf[kst][2] = pack_half2(s[2 * kst + 1][0], s[2 * kst + 1][1]);
            pf[kst][3] = pack_half2(s[2 * kst + 1][2], s[2 * kst + 1][3]);
        }

#pragma unroll
        for (int g = 0; g < 4; ++g) {
#pragma unroll
            for (int kst = 0; kst < 4; ++kst) {
                uint32_t b0, b1, b2, b3;
                ldsm_x4t(b0, b1, b2, b3,
                         smem_u32(&Vs[cur][kst * 16 + (lane & 15)][g * 16 + (lane >> 4) * 8]));
                uint32_t bfa[2] = {b0, b1}, bfb[2] = {b2, b3};
                mma_f16(o[2 * g],     pf[kst], bfa);
                mma_f16(o[2 * g + 1], pf[kst], bfb);
            }
        }
    }

    float inv1 = 1.0f / l1, inv2 = 1.0f / l2;
#pragma unroll
    for (int dt = 0; dt < 8; ++dt) {
        int col = h * DH_ + dt * 8 + 2 * t4;
        *(__half2*)&g_ctxh[(size_t)(b * N_ + qg1) * D_ + col] =
            __floats2half2_rn(o[dt][0] * inv1, o[dt][1] * inv1);
        *(__half2*)&g_ctxh[(size_t)(b * N_ + qg2) * D_ + col] =
            __floats2half2_rn(o[dt][2] * inv2, o[dt][3] * inv2);
    }
}

// -------------------- launch -------------------------------------------------
extern "C" void kernel_launch(void* const* d_in, const int* in_sizes, int n_in,
                              void* d_out, int out_size) {
    const float* states     = (const float*)d_in[0];
    const float* key_states = (const float*)d_in[1];
    const int*   ab         = (const int*)d_in[3];
    const float* Wq         = (const float*)d_in[4];
    const float* Wk         = (const float*)d_in[5];
    const float* Wv         = (const float*)d_in[6];
    const float* Wo         = (const float*)d_in[7];
    const float* bias_embs  = (const float*)d_in[8];
    const float* bias_scal  = (const float*)d_in[9];
    float* out = (float*)d_out;

    float *gbias, *gsk;
    cudaGetSymbolAddress((void**)&gbias, g_bias);
    cudaGetSymbolAddress((void**)&gsk,   g_sk);

    cudaFuncSetAttribute(qkv_gemm_kernel,
                         cudaFuncAttributeMaxDynamicSharedMemorySize, SMEM_G(4));
    cudaFuncSetAttribute(out_gemm_kernel,
                         cudaFuncAttributeMaxDynamicSharedMemorySize, SMEM_G(2));

    cudaMemsetAsync(gbias, 0, sizeof(float) * B_ * N_ * N_, 0);
    cudaMemsetAsync(gsk,   0, sizeof(float) * BN_ * H_, 0);

    prep_kernel<<<3200, 256>>>(Wq, Wk, Wv, Wo, ab, bias_embs, bias_scal, gbias,
                               states, key_states);

    dim3 qkvgrid(BN_ / 128, D_ / 128, 3);
    qkv_gemm_kernel<<<qkvgrid, 256, SMEM_G(4)>>>();

    attn_kernel<<<512, 128>>>(gbias);

    dim3 ogrid(BN_ / 64, D_ / 128);   // 256 blocks
    out_gemm_kernel<<<ogrid, 256, SMEM_G(2)>>>(out);
}